// round 13
// baseline (speedup 1.0000x reference)
#include <cuda_runtime.h>
#include <cuda_fp16.h>
#include <math_constants.h>
#include <cstdint>

// ---------------------------------------------------------------------------
// MultiheadAttention (T=2048, B=2, E=1024, H=16, D=64) fp32, all-fp16 HMMA.
// R13: longer MMA runs per barrier — GEMM BK=128 (128 MMAs/warp/iter),
// attention KV-stage 128 (softmax bookkeeping halved).
// ---------------------------------------------------------------------------

#define EMBED   1024
#define NHEAD   16
#define HDIM    64
#define TLEN    2048
#define BSZ     2
#define MROWS   4096
#define QKV_N   3072

// ------------------------------- scratch -----------------------------------
__device__ __half g_xh  [(size_t)MROWS * EMBED];
__device__ __half g_winh[(size_t)QKV_N * EMBED];
__device__ __half g_woh [(size_t)EMBED * EMBED];
__device__ __half g_qkvh[(size_t)MROWS * QKV_N];
__device__ __half g_ah  [(size_t)MROWS * EMBED];

// --------------------------- asm helpers -----------------------------------
__device__ __forceinline__ uint32_t smem_u32(const void* p) {
    uint32_t a;
    asm("{ .reg .u64 t; cvta.to.shared.u64 t, %1; cvt.u32.u64 %0, t; }"
        : "=r"(a) : "l"(p));
    return a;
}
__device__ __forceinline__ void ldsm4(uint32_t* r, uint32_t a) {
    asm volatile("ldmatrix.sync.aligned.m8n8.x4.shared.b16 {%0,%1,%2,%3}, [%4];"
        : "=r"(r[0]), "=r"(r[1]), "=r"(r[2]), "=r"(r[3]) : "r"(a));
}
__device__ __forceinline__ void ldsm4t(uint32_t* r, uint32_t a) {
    asm volatile("ldmatrix.sync.aligned.m8n8.x4.trans.shared.b16 {%0,%1,%2,%3}, [%4];"
        : "=r"(r[0]), "=r"(r[1]), "=r"(r[2]), "=r"(r[3]) : "r"(a));
}
__device__ __forceinline__ void mma_f16(float* c, const uint32_t* a, const uint32_t* b) {
    asm volatile(
        "mma.sync.aligned.m16n8k16.row.col.f32.f16.f16.f32 "
        "{%0,%1,%2,%3}, {%4,%5,%6,%7}, {%8,%9}, {%0,%1,%2,%3};"
        : "+f"(c[0]), "+f"(c[1]), "+f"(c[2]), "+f"(c[3])
        : "r"(a[0]), "r"(a[1]), "r"(a[2]), "r"(a[3]), "r"(b[0]), "r"(b[1]));
}
__device__ __forceinline__ void cpa16(uint32_t dst, const void* src) {
    asm volatile("cp.async.cg.shared.global [%0], [%1], 16;" :: "r"(dst), "l"(src));
}
#define CP_COMMIT() asm volatile("cp.async.commit_group;")
#define CP_WAIT0()  asm volatile("cp.async.wait_group 0;")

__device__ __forceinline__ uint32_t packh(float x, float y) {
    __half2 t = __floats2half2_rn(x, y);
    return *(uint32_t*)&t;
}
__device__ __forceinline__ uint32_t h2ex2(uint32_t x) {
    uint32_t y;
    asm("ex2.approx.f16x2 %0, %1;" : "=r"(y) : "r"(x));
    return y;
}

// ---------------------------------------------------------------------------
__global__ void __launch_bounds__(256) conv_f16(
    const float* __restrict__ src, __half* __restrict__ dst, int n8)
{
    int i = blockIdx.x * 256 + threadIdx.x;
    if (i >= n8) return;
    float4 a = *(const float4*)(src + (size_t)i * 8);
    float4 b = *(const float4*)(src + (size_t)i * 8 + 4);
    __half2 h[4];
    h[0] = __floats2half2_rn(a.x, a.y); h[1] = __floats2half2_rn(a.z, a.w);
    h[2] = __floats2half2_rn(b.x, b.y); h[3] = __floats2half2_rn(b.z, b.w);
    *(uint4*)(dst + (size_t)i * 8) = *(uint4*)h;
}

// ---------------------------------------------------------------------------
// fp16 GEMM-NT + bias: 128x128 CTA tile, BK=128, 8 warps (2x4), warp tile
// 64x32, cp.async 2-stage. 128 MMAs/warp between barriers.
// MODE 0: fp32 out.  MODE 2: fp16 out.
// ---------------------------------------------------------------------------
#define GST    136                   // fp16 row stride (272 B)
#define GTILE  (128 * GST * 2)       // 34816 B
#define GSTG   (2 * GTILE)           // 69632 B per stage

template<int MODE>
__global__ void __launch_bounds__(256) gemm_f16(
    const __half* __restrict__ A, const __half* __restrict__ B,
    const float* __restrict__ bias, float* __restrict__ Cf,
    __half* __restrict__ Ch, int N, int K)
{
    extern __shared__ char smem[];
    const uint32_t sbase = smem_u32(smem);
    const int tid = threadIdx.x, wid = tid >> 5, lane = tid & 31;
    const int bm = blockIdx.y, bn = blockIdx.x;
    const int wm = wid >> 2, wn = wid & 3;

    float acc[4][4][4];
#pragma unroll
    for (int a = 0; a < 4; a++)
#pragma unroll
        for (int b = 0; b < 4; b++)
#pragma unroll
            for (int c = 0; c < 4; c++) acc[a][b][c] = 0.0f;

    // 2 tensors x 128 rows x 128 cols fp16 = 4096 x 16B transfers, 16/thread.
    auto prefetch = [&](int it) {
        const int k0 = it << 7;
        const int buf = it & 1;
#pragma unroll
        for (int i = 0; i < 16; i++) {
            int g = tid + i * 256;           // 0..4095
            int t = g >> 11;                 // 0=A, 1=B (uniform per i)
            int c = g & 2047;
            int row = c >> 4, ch = c & 15;
            const __half* P = t ? B : A;
            int rb = t ? bn * 128 : bm * 128;
            const void* src = P + (size_t)(rb + row) * K + k0 + ch * 8;
            uint32_t dst = sbase + buf * GSTG + t * GTILE
                         + (row * GST + ch * 8) * 2;
            cpa16(dst, src);
        }
        CP_COMMIT();
    };

    const int niter = K >> 7;
    prefetch(0);
    for (int it = 0; it < niter; it++) {
        CP_WAIT0();
        __syncthreads();
        if (it + 1 < niter) prefetch(it + 1);

        const uint32_t tA = sbase + (it & 1) * GSTG;
        const uint32_t tB = tA + GTILE;

        const int ar = lane & 15, ac = (lane >> 4) * 8;
        const int br = (lane & 7) + ((lane & 16) ? 8 : 0);
        const int bc = (lane & 8) ? 8 : 0;

#pragma unroll
        for (int ks = 0; ks < 8; ks++) {
            const int k0 = ks * 16;
            uint32_t ah[4][4], bh[4][2];
#pragma unroll
            for (int mi = 0; mi < 4; mi++)
                ldsm4(ah[mi], tA + ((wm * 64 + mi * 16 + ar) * GST + k0 + ac) * 2);
#pragma unroll
            for (int p = 0; p < 2; p++) {
                uint32_t r[4];
                ldsm4(r, tB + ((wn * 32 + p * 16 + br) * GST + k0 + bc) * 2);
                bh[2*p][0] = r[0]; bh[2*p][1] = r[1];
                bh[2*p+1][0] = r[2]; bh[2*p+1][1] = r[3];
            }
#pragma unroll
            for (int mi = 0; mi < 4; mi++)
#pragma unroll
                for (int ni = 0; ni < 4; ni++)
                    mma_f16(acc[mi][ni], ah[mi], bh[ni]);
        }
    }

    const int r = lane >> 2, q = lane & 3;
#pragma unroll
    for (int mi = 0; mi < 4; mi++) {
#pragma unroll
        for (int ni = 0; ni < 4; ni++) {
            int row = bm * 128 + wm * 64 + mi * 16 + r;
            int col = bn * 128 + wn * 32 + ni * 8 + 2 * q;
            float b0 = bias[col], b1 = bias[col + 1];
            float v0 = acc[mi][ni][0] + b0, v1 = acc[mi][ni][1] + b1;
            float v2 = acc[mi][ni][2] + b0, v3 = acc[mi][ni][3] + b1;
            if (MODE == 0) {
                *(float2*)(Cf + (size_t)row * N + col)       = make_float2(v0, v1);
                *(float2*)(Cf + (size_t)(row + 8) * N + col) = make_float2(v2, v3);
            } else {
                *(__half2*)(Ch + (size_t)row * N + col)       = __floats2half2_rn(v0, v1);
                *(__half2*)(Ch + (size_t)(row + 8) * N + col) = __floats2half2_rn(v2, v3);
            }
        }
    }
}

// ---------------------------------------------------------------------------
// Flash attention, fp16 HMMA, log2-domain softmax, KV-stage 128.
// Block = (q-tile 128, b*H+h), 256 threads / 8 warps; warp w owns q rows
// 16w..16w+15. One softmax update per 128 kv cols.
// ---------------------------------------------------------------------------
#define AST   72
#define ATBF  (128 * AST * 2)    // 18432 B per K/V tile (128 rows)
#define QSTG  (128 * AST * 2)    // 18432 B

__global__ void __launch_bounds__(256) attn_f16(
    const __half* __restrict__ qkv, __half* __restrict__ oh)
{
    extern __shared__ char smem[];
    const uint32_t sb  = smem_u32(smem);
    const uint32_t sQ  = sb;
    const uint32_t sKV = sb + QSTG;

    const int tid = threadIdx.x, wid = tid >> 5, lane = tid & 31;
    const int qt = blockIdx.x, bh = blockIdx.y, b = bh >> 4, h = bh & 15;

    // K tile + V tile (128 rows each) per stage = 2048 x 16B, 8/thread.
    auto pf = [&](int st) {
        const int buf = st & 1;
#pragma unroll
        for (int i = 0; i < 8; i++) {
            int c  = tid + i * 256;        // 0..2047
            int kv = c >> 10;              // 0=K, 1=V
            int e  = c & 1023;
            int row = e >> 3, ch = e & 7;  // row 0..127
            const void* src = qkv + ((size_t)((st * 128 + row) * 2 + b)) * QKV_N
                            + (kv ? 2 * EMBED : EMBED) + h * 64 + ch * 8;
            uint32_t dst = sKV + (buf * 2 + kv) * ATBF + (row * AST + ch * 8) * 2;
            cpa16(dst, src);
        }
        CP_COMMIT();
    };

    pf(0);

    // Q scaled by 0.125 * log2(e): scores leave QK^T in log2 domain.
    const __half2 s2 = __floats2half2_rn(0.1803368801f, 0.1803368801f);
#pragma unroll
    for (int i = 0; i < 4; i++) {
        int c = tid + i * 256;
        int row = c >> 3, ch = c & 7;
        int t = qt * 128 + row;
        uint4 v = *(const uint4*)(qkv + ((size_t)(t * 2 + b)) * QKV_N + h * 64 + ch * 8);
        __half2* p = (__half2*)&v;
#pragma unroll
        for (int j = 0; j < 4; j++) p[j] = __hmul2(p[j], s2);
        *(uint4*)(smem + (row * AST + ch * 8) * 2) = v;
    }
    __syncthreads();

    uint32_t qf[4][4];
    {
        const int ar = lane & 15, ac = (lane >> 4) * 8;
#pragma unroll
        for (int kt = 0; kt < 4; kt++)
            ldsm4(qf[kt], sQ + ((wid * 16 + ar) * AST + kt * 16 + ac) * 2);
    }

    float O[8][4];
#pragma unroll
    for (int i = 0; i < 8; i++)
#pragma unroll
        for (int j = 0; j < 4; j++) O[i][j] = 0.0f;
    float m0 = -CUDART_INF_F, m1 = -CUDART_INF_F, l0 = 0.0f, l1 = 0.0f;

    const int br = (lane & 7) + ((lane & 16) ? 8 : 0);
    const int bc = (lane & 8) ? 8 : 0;
    const int vr = lane & 15, vc = (lane >> 4) * 8;

    for (int st = 0; st < TLEN / 128; st++) {
        CP_WAIT0();
        __syncthreads();
        if (st + 1 < TLEN / 128) pf(st + 1);

        const uint32_t sK = sKV + ((st & 1) * 2) * ATBF;
        const uint32_t sV = sK + ATBF;

        // ---- S = Q K^T over 128 kv cols ----
        float s4[16][4];
#pragma unroll
        for (int i = 0; i < 16; i++)
#pragma unroll
            for (int j = 0; j < 4; j++) s4[i][j] = 0.0f;

#pragma unroll
        for (int kt = 0; kt < 4; kt++) {
            uint32_t kh[16][2];
#pragma unroll
            for (int p = 0; p < 8; p++) {
                uint32_t r[4];
                ldsm4(r, sK + ((p * 16 + br) * AST + kt * 16 + bc) * 2);
                kh[2*p][0] = r[0]; kh[2*p][1] = r[1];
                kh[2*p+1][0] = r[2]; kh[2*p+1][1] = r[3];
            }
#pragma unroll
            for (int nt = 0; nt < 16; nt++)
                mma_f16(s4[nt], qf[kt], kh[nt]);
        }

        // ---- online softmax (one update per 128 cols) ----
        float mx0 = -CUDART_INF_F, mx1 = -CUDART_INF_F;
#pragma unroll
        for (int nt = 0; nt < 16; nt++) {
            mx0 = fmaxf(mx0, fmaxf(s4[nt][0], s4[nt][1]));
            mx1 = fmaxf(mx1, fmaxf(s4[nt][2], s4[nt][3]));
        }
        mx0 = fmaxf(mx0, __shfl_xor_sync(0xffffffffu, mx0, 1));
        mx0 = fmaxf(mx0, __shfl_xor_sync(0xffffffffu, mx0, 2));
        mx1 = fmaxf(mx1, __shfl_xor_sync(0xffffffffu, mx1, 1));
        mx1 = fmaxf(mx1, __shfl_xor_sync(0xffffffffu, mx1, 2));

        float mn0 = fmaxf(m0, mx0), mn1 = fmaxf(m1, mx1);
        float a0 = exp2f(m0 - mn0), a1 = exp2f(m1 - mn1);
        m0 = mn0; m1 = mn1;

        uint32_t pa[8][4];
        float sum0 = 0.0f, sum1 = 0.0f;
#pragma unroll
        for (int jj = 0; jj < 8; jj++) {
            pa[jj][0] = h2ex2(packh(s4[2*jj][0]   - mn0, s4[2*jj][1]   - mn0));
            pa[jj][1] = h2ex2(packh(s4[2*jj][2]   - mn1, s4[2*jj][3]   - mn1));
            pa[jj][2] = h2ex2(packh(s4[2*jj+1][0] - mn0, s4[2*jj+1][1] - mn0));
            pa[jj][3] = h2ex2(packh(s4[2*jj+1][2] - mn1, s4[2*jj+1][3] - mn1));
            float2 f;
            f = __half22float2(*(__half2*)&pa[jj][0]); sum0 += f.x + f.y;
            f = __half22float2(*(__half2*)&pa[jj][2]); sum0 += f.x + f.y;
            f = __half22float2(*(__half2*)&pa[jj][1]); sum1 += f.x + f.y;
            f = __half22float2(*(__half2*)&pa[jj][3]); sum1 += f.x + f.y;
        }
        sum0 += __shfl_xor_sync(0xffffffffu, sum0, 1);
        sum0 += __shfl_xor_sync(0xffffffffu, sum0, 2);
        sum1 += __shfl_xor_sync(0xffffffffu, sum1, 1);
        sum1 += __shfl_xor_sync(0xffffffffu, sum1, 2);
        l0 = l0 * a0 + sum0;
        l1 = l1 * a1 + sum1;
#pragma unroll
        for (int nt = 0; nt < 8; nt++) {
            O[nt][0] *= a0; O[nt][1] *= a0; O[nt][2] *= a1; O[nt][3] *= a1;
        }

        // ---- O += P V (c-dim 128) ----
#pragma unroll
        for (int kt = 0; kt < 8; kt++) {
#pragma unroll
            for (int p = 0; p < 4; p++) {
                uint32_t r[4];
                ldsm4t(r, sV + ((kt * 16 + vr) * AST + p * 16 + vc) * 2);
                mma_f16(O[2*p],   pa[kt], r);
                mma_f16(O[2*p+1], pa[kt], r + 2);
            }
        }
    }

    const float inv0 = 1.0f / l0, inv1 = 1.0f / l1;
    const int r = lane >> 2, q = lane & 3;
    const int t0 = qt * 128 + wid * 16 + r;
#pragma unroll
    for (int nt = 0; nt < 8; nt++) {
        int d = nt * 8 + 2 * q;
        size_t i0 = ((size_t)(t0 * 2 + b)) * EMBED + h * 64 + d;
        size_t i1 = ((size_t)((t0 + 8) * 2 + b)) * EMBED + h * 64 + d;
        *(__half2*)(oh + i0) = __floats2half2_rn(O[nt][0] * inv0, O[nt][1] * inv0);
        *(__half2*)(oh + i1) = __floats2half2_rn(O[nt][2] * inv1, O[nt][3] * inv1);
    }
}

// ---------------------------------------------------------------------------
extern "C" void kernel_launch(void* const* d_in, const int* in_sizes, int n_in,
                              void* d_out, int out_size)
{
    const float* x     = (const float*)d_in[0];
    const float* w_in  = (const float*)d_in[1];
    const float* b_in  = (const float*)d_in[2];
    const float* w_out = (const float*)d_in[3];
    const float* b_out = (const float*)d_in[4];
    float* out = (float*)d_out;

    void *xh, *winh, *woh, *qkvh, *ah;
    cudaGetSymbolAddress(&xh, g_xh);
    cudaGetSymbolAddress(&winh, g_winh);
    cudaGetSymbolAddress(&woh, g_woh);
    cudaGetSymbolAddress(&qkvh, g_qkvh);
    cudaGetSymbolAddress(&ah, g_ah);

    const int gemm_smem = 2 * GSTG;                   // 139264
    const int attn_smem = QSTG + 4 * ATBF;            // 92160
    cudaFuncSetAttribute(gemm_f16<0>,
        cudaFuncAttributeMaxDynamicSharedMemorySize, gemm_smem);
    cudaFuncSetAttribute(gemm_f16<2>,
        cudaFuncAttributeMaxDynamicSharedMemorySize, gemm_smem);
    cudaFuncSetAttribute(attn_f16,
        cudaFuncAttributeMaxDynamicSharedMemorySize, attn_smem);

    int n8 = MROWS * EMBED / 8;
    conv_f16<<<(n8 + 255) / 256, 256>>>(x, (__half*)xh, n8);
    n8 = QKV_N * EMBED / 8;
    conv_f16<<<(n8 + 255) / 256, 256>>>(w_in, (__half*)winh, n8);
    n8 = EMBED * EMBED / 8;
    conv_f16<<<(n8 + 255) / 256, 256>>>(w_out, (__half*)woh, n8);

    // 1) QKV projection -> fp16 qkv
    gemm_f16<2><<<dim3(QKV_N / 128, MROWS / 128), 256, gemm_smem>>>(
        (const __half*)xh, (const __half*)winh, b_in,
        nullptr, (__half*)qkvh, QKV_N, EMBED);

    // 2) attention -> fp16
    attn_f16<<<dim3(TLEN / 128, BSZ * NHEAD), 256, attn_smem>>>(
        (const __half*)qkvh, (__half*)ah);

    // 3) output projection -> fp32 out
    gemm_f16<0><<<dim3(EMBED / 128, MROWS / 128), 256, gemm_smem>>>(
        (const __half*)ah, (const __half*)woh, b_out,
        out, nullptr, EMBED, EMBED);
}

// round 14
// speedup vs baseline: 1.1418x; 1.1418x over previous
#include <cuda_runtime.h>
#include <cuda_fp16.h>
#include <math_constants.h>
#include <cstdint>

// ---------------------------------------------------------------------------
// MultiheadAttention (T=2048, B=2, E=1024, H=16, D=64) fp32, all-fp16 HMMA.
// R14: best-of composition — R11 GEMM (BK=64, 8 warps, 2 CTAs/SM) +
// R12 attention (4 warps, 32 q-rows/warp).
// ---------------------------------------------------------------------------

#define EMBED   1024
#define NHEAD   16
#define HDIM    64
#define TLEN    2048
#define BSZ     2
#define MROWS   4096
#define QKV_N   3072

// ------------------------------- scratch -----------------------------------
__device__ __half g_xh  [(size_t)MROWS * EMBED];
__device__ __half g_winh[(size_t)QKV_N * EMBED];
__device__ __half g_woh [(size_t)EMBED * EMBED];
__device__ __half g_qkvh[(size_t)MROWS * QKV_N];
__device__ __half g_ah  [(size_t)MROWS * EMBED];

// --------------------------- asm helpers -----------------------------------
__device__ __forceinline__ uint32_t smem_u32(const void* p) {
    uint32_t a;
    asm("{ .reg .u64 t; cvta.to.shared.u64 t, %1; cvt.u32.u64 %0, t; }"
        : "=r"(a) : "l"(p));
    return a;
}
__device__ __forceinline__ void ldsm4(uint32_t* r, uint32_t a) {
    asm volatile("ldmatrix.sync.aligned.m8n8.x4.shared.b16 {%0,%1,%2,%3}, [%4];"
        : "=r"(r[0]), "=r"(r[1]), "=r"(r[2]), "=r"(r[3]) : "r"(a));
}
__device__ __forceinline__ void ldsm4t(uint32_t* r, uint32_t a) {
    asm volatile("ldmatrix.sync.aligned.m8n8.x4.trans.shared.b16 {%0,%1,%2,%3}, [%4];"
        : "=r"(r[0]), "=r"(r[1]), "=r"(r[2]), "=r"(r[3]) : "r"(a));
}
__device__ __forceinline__ void mma_f16(float* c, const uint32_t* a, const uint32_t* b) {
    asm volatile(
        "mma.sync.aligned.m16n8k16.row.col.f32.f16.f16.f32 "
        "{%0,%1,%2,%3}, {%4,%5,%6,%7}, {%8,%9}, {%0,%1,%2,%3};"
        : "+f"(c[0]), "+f"(c[1]), "+f"(c[2]), "+f"(c[3])
        : "r"(a[0]), "r"(a[1]), "r"(a[2]), "r"(a[3]), "r"(b[0]), "r"(b[1]));
}
__device__ __forceinline__ void cpa16(uint32_t dst, const void* src) {
    asm volatile("cp.async.cg.shared.global [%0], [%1], 16;" :: "r"(dst), "l"(src));
}
#define CP_COMMIT() asm volatile("cp.async.commit_group;")
#define CP_WAIT0()  asm volatile("cp.async.wait_group 0;")

__device__ __forceinline__ uint32_t packh(float x, float y) {
    __half2 t = __floats2half2_rn(x, y);
    return *(uint32_t*)&t;
}
__device__ __forceinline__ uint32_t h2ex2(uint32_t x) {
    uint32_t y;
    asm("ex2.approx.f16x2 %0, %1;" : "=r"(y) : "r"(x));
    return y;
}

// ---------------------------------------------------------------------------
__global__ void __launch_bounds__(256) conv_f16(
    const float* __restrict__ src, __half* __restrict__ dst, int n8)
{
    int i = blockIdx.x * 256 + threadIdx.x;
    if (i >= n8) return;
    float4 a = *(const float4*)(src + (size_t)i * 8);
    float4 b = *(const float4*)(src + (size_t)i * 8 + 4);
    __half2 h[4];
    h[0] = __floats2half2_rn(a.x, a.y); h[1] = __floats2half2_rn(a.z, a.w);
    h[2] = __floats2half2_rn(b.x, b.y); h[3] = __floats2half2_rn(b.z, b.w);
    *(uint4*)(dst + (size_t)i * 8) = *(uint4*)h;
}

// ---------------------------------------------------------------------------
// fp16 GEMM-NT + bias (R11 config): 128x128 CTA tile, BK=64, 8 warps (2x4),
// warp tile 64x32, cp.async 2-stage. MODE 0: fp32 out.  MODE 2: fp16 out.
// ---------------------------------------------------------------------------
#define GST    72
#define GTILE  (128 * GST * 2)       // 18432 B
#define GSTG   (2 * GTILE)           // 36864 B per stage

template<int MODE>
__global__ void __launch_bounds__(256) gemm_f16(
    const __half* __restrict__ A, const __half* __restrict__ B,
    const float* __restrict__ bias, float* __restrict__ Cf,
    __half* __restrict__ Ch, int N, int K)
{
    extern __shared__ char smem[];
    const uint32_t sbase = smem_u32(smem);
    const int tid = threadIdx.x, wid = tid >> 5, lane = tid & 31;
    const int bm = blockIdx.y, bn = blockIdx.x;
    const int wm = wid >> 2, wn = wid & 3;

    float acc[4][4][4];
#pragma unroll
    for (int a = 0; a < 4; a++)
#pragma unroll
        for (int b = 0; b < 4; b++)
#pragma unroll
            for (int c = 0; c < 4; c++) acc[a][b][c] = 0.0f;

    auto prefetch = [&](int it) {
        const int k0 = it << 6;
        const int buf = it & 1;
#pragma unroll
        for (int i = 0; i < 8; i++) {
            int g = tid + i * 256;           // 0..2047
            int t = g >> 10;                 // 0=A, 1=B (uniform per i)
            int c = g & 1023;
            int row = c >> 3, ch = c & 7;
            const __half* P = t ? B : A;
            int rb = t ? bn * 128 : bm * 128;
            const void* src = P + (size_t)(rb + row) * K + k0 + ch * 8;
            uint32_t dst = sbase + buf * GSTG + t * GTILE
                         + (row * GST + ch * 8) * 2;
            cpa16(dst, src);
        }
        CP_COMMIT();
    };

    const int niter = K >> 6;
    prefetch(0);
    for (int it = 0; it < niter; it++) {
        CP_WAIT0();
        __syncthreads();
        if (it + 1 < niter) prefetch(it + 1);

        const uint32_t tA = sbase + (it & 1) * GSTG;
        const uint32_t tB = tA + GTILE;

        const int ar = lane & 15, ac = (lane >> 4) * 8;
        const int br = (lane & 7) + ((lane & 16) ? 8 : 0);
        const int bc = (lane & 8) ? 8 : 0;

#pragma unroll
        for (int ks = 0; ks < 4; ks++) {
            const int k0 = ks * 16;
            uint32_t ah[4][4], bh[4][2];
#pragma unroll
            for (int mi = 0; mi < 4; mi++)
                ldsm4(ah[mi], tA + ((wm * 64 + mi * 16 + ar) * GST + k0 + ac) * 2);
#pragma unroll
            for (int p = 0; p < 2; p++) {
                uint32_t r[4];
                ldsm4(r, tB + ((wn * 32 + p * 16 + br) * GST + k0 + bc) * 2);
                bh[2*p][0] = r[0]; bh[2*p][1] = r[1];
                bh[2*p+1][0] = r[2]; bh[2*p+1][1] = r[3];
            }
#pragma unroll
            for (int mi = 0; mi < 4; mi++)
#pragma unroll
                for (int ni = 0; ni < 4; ni++)
                    mma_f16(acc[mi][ni], ah[mi], bh[ni]);
        }
    }

    const int r = lane >> 2, q = lane & 3;
#pragma unroll
    for (int mi = 0; mi < 4; mi++) {
#pragma unroll
        for (int ni = 0; ni < 4; ni++) {
            int row = bm * 128 + wm * 64 + mi * 16 + r;
            int col = bn * 128 + wn * 32 + ni * 8 + 2 * q;
            float b0 = bias[col], b1 = bias[col + 1];
            float v0 = acc[mi][ni][0] + b0, v1 = acc[mi][ni][1] + b1;
            float v2 = acc[mi][ni][2] + b0, v3 = acc[mi][ni][3] + b1;
            if (MODE == 0) {
                *(float2*)(Cf + (size_t)row * N + col)       = make_float2(v0, v1);
                *(float2*)(Cf + (size_t)(row + 8) * N + col) = make_float2(v2, v3);
            } else {
                *(__half2*)(Ch + (size_t)row * N + col)       = __floats2half2_rn(v0, v1);
                *(__half2*)(Ch + (size_t)(row + 8) * N + col) = __floats2half2_rn(v2, v3);
            }
        }
    }
}

// ---------------------------------------------------------------------------
// Flash attention (R12 config): fp16 HMMA, log2-domain softmax, 128 threads /
// 4 warps; warp w owns q rows 32w..32w+31.
// ---------------------------------------------------------------------------
#define AST  72
#define ATBF (64 * AST * 2)     // 9216 B per K/V tile
#define QSTG (128 * AST * 2)    // 18432 B

__global__ void __launch_bounds__(128) attn_f16(
    const __half* __restrict__ qkv, __half* __restrict__ oh)
{
    extern __shared__ char smem[];
    const uint32_t sb  = smem_u32(smem);
    const uint32_t sQ  = sb;
    const uint32_t sKV = sb + QSTG;

    const int tid = threadIdx.x, wid = tid >> 5, lane = tid & 31;
    const int qt = blockIdx.x, bh = blockIdx.y, b = bh >> 4, h = bh & 15;

    auto pf = [&](int st) {
        const int buf = st & 1;
#pragma unroll
        for (int i = 0; i < 8; i++) {
            int c  = tid + i * 128;        // 0..1023
            int kv = c >> 9;               // 0=K, 1=V
            int e  = c & 511;
            int row = e >> 3, ch = e & 7;
            const void* src = qkv + ((size_t)((st * 64 + row) * 2 + b)) * QKV_N
                            + (kv ? 2 * EMBED : EMBED) + h * 64 + ch * 8;
            uint32_t dst = sKV + (buf * 2 + kv) * ATBF + (row * AST + ch * 8) * 2;
            cpa16(dst, src);
        }
        CP_COMMIT();
    };

    pf(0);

    const __half2 s2 = __floats2half2_rn(0.1803368801f, 0.1803368801f);
#pragma unroll
    for (int i = 0; i < 8; i++) {
        int c = tid + i * 128;
        int row = c >> 3, ch = c & 7;
        int t = qt * 128 + row;
        uint4 v = *(const uint4*)(qkv + ((size_t)(t * 2 + b)) * QKV_N + h * 64 + ch * 8);
        __half2* p = (__half2*)&v;
#pragma unroll
        for (int j = 0; j < 4; j++) p[j] = __hmul2(p[j], s2);
        *(uint4*)(smem + (row * AST + ch * 8) * 2) = v;
    }
    __syncthreads();

    uint32_t qf[4][2][4];
    {
        const int ar = lane & 15, ac = (lane >> 4) * 8;
#pragma unroll
        for (int kt = 0; kt < 4; kt++)
#pragma unroll
            for (int mi = 0; mi < 2; mi++)
                ldsm4(qf[kt][mi],
                      sQ + ((wid * 32 + mi * 16 + ar) * AST + kt * 16 + ac) * 2);
    }

    float O[2][8][4];
#pragma unroll
    for (int mi = 0; mi < 2; mi++)
#pragma unroll
        for (int i = 0; i < 8; i++)
#pragma unroll
            for (int j = 0; j < 4; j++) O[mi][i][j] = 0.0f;
    float m[4], l[4];
#pragma unroll
    for (int i = 0; i < 4; i++) { m[i] = -CUDART_INF_F; l[i] = 0.0f; }

    const int br = (lane & 7) + ((lane & 16) ? 8 : 0);
    const int bc = (lane & 8) ? 8 : 0;
    const int vr = lane & 15, vc = (lane >> 4) * 8;

    for (int st = 0; st < TLEN / 64; st++) {
        CP_WAIT0();
        __syncthreads();
        if (st + 1 < TLEN / 64) pf(st + 1);

        const uint32_t sK = sKV + ((st & 1) * 2) * ATBF;
        const uint32_t sV = sK + ATBF;

        float s4[2][8][4];
#pragma unroll
        for (int mi = 0; mi < 2; mi++)
#pragma unroll
            for (int i = 0; i < 8; i++)
#pragma unroll
                for (int j = 0; j < 4; j++) s4[mi][i][j] = 0.0f;

#pragma unroll
        for (int kt = 0; kt < 4; kt++) {
            uint32_t kh[8][2];
#pragma unroll
            for (int p = 0; p < 4; p++) {
                uint32_t r[4];
                ldsm4(r, sK + ((p * 16 + br) * AST + kt * 16 + bc) * 2);
                kh[2*p][0] = r[0]; kh[2*p][1] = r[1];
                kh[2*p+1][0] = r[2]; kh[2*p+1][1] = r[3];
            }
#pragma unroll
            for (int mi = 0; mi < 2; mi++)
#pragma unroll
                for (int nt = 0; nt < 8; nt++)
                    mma_f16(s4[mi][nt], qf[kt][mi], kh[nt]);
        }

        uint32_t pa[2][4][4];
#pragma unroll
        for (int mi = 0; mi < 2; mi++) {
            float mx0 = -CUDART_INF_F, mx1 = -CUDART_INF_F;
#pragma unroll
            for (int nt = 0; nt < 8; nt++) {
                mx0 = fmaxf(mx0, fmaxf(s4[mi][nt][0], s4[mi][nt][1]));
                mx1 = fmaxf(mx1, fmaxf(s4[mi][nt][2], s4[mi][nt][3]));
            }
            mx0 = fmaxf(mx0, __shfl_xor_sync(0xffffffffu, mx0, 1));
            mx0 = fmaxf(mx0, __shfl_xor_sync(0xffffffffu, mx0, 2));
            mx1 = fmaxf(mx1, __shfl_xor_sync(0xffffffffu, mx1, 1));
            mx1 = fmaxf(mx1, __shfl_xor_sync(0xffffffffu, mx1, 2));

            float mn0 = fmaxf(m[mi*2],   mx0);
            float mn1 = fmaxf(m[mi*2+1], mx1);
            float a0 = exp2f(m[mi*2]   - mn0);
            float a1 = exp2f(m[mi*2+1] - mn1);
            m[mi*2] = mn0; m[mi*2+1] = mn1;

            float sum0 = 0.0f, sum1 = 0.0f;
#pragma unroll
            for (int jj = 0; jj < 4; jj++) {
                pa[mi][jj][0] = h2ex2(packh(s4[mi][2*jj][0]   - mn0, s4[mi][2*jj][1]   - mn0));
                pa[mi][jj][1] = h2ex2(packh(s4[mi][2*jj][2]   - mn1, s4[mi][2*jj][3]   - mn1));
                pa[mi][jj][2] = h2ex2(packh(s4[mi][2*jj+1][0] - mn0, s4[mi][2*jj+1][1] - mn0));
                pa[mi][jj][3] = h2ex2(packh(s4[mi][2*jj+1][2] - mn1, s4[mi][2*jj+1][3] - mn1));
                float2 f;
                f = __half22float2(*(__half2*)&pa[mi][jj][0]); sum0 += f.x + f.y;
                f = __half22float2(*(__half2*)&pa[mi][jj][2]); sum0 += f.x + f.y;
                f = __half22float2(*(__half2*)&pa[mi][jj][1]); sum1 += f.x + f.y;
                f = __half22float2(*(__half2*)&pa[mi][jj][3]); sum1 += f.x + f.y;
            }
            sum0 += __shfl_xor_sync(0xffffffffu, sum0, 1);
            sum0 += __shfl_xor_sync(0xffffffffu, sum0, 2);
            sum1 += __shfl_xor_sync(0xffffffffu, sum1, 1);
            sum1 += __shfl_xor_sync(0xffffffffu, sum1, 2);
            l[mi*2]   = l[mi*2]   * a0 + sum0;
            l[mi*2+1] = l[mi*2+1] * a1 + sum1;
#pragma unroll
            for (int nt = 0; nt < 8; nt++) {
                O[mi][nt][0] *= a0; O[mi][nt][1] *= a0;
                O[mi][nt][2] *= a1; O[mi][nt][3] *= a1;
            }
        }

#pragma unroll
        for (int kt = 0; kt < 4; kt++) {
#pragma unroll
            for (int p = 0; p < 4; p++) {
                uint32_t r[4];
                ldsm4t(r, sV + ((kt * 16 + vr) * AST + p * 16 + vc) * 2);
#pragma unroll
                for (int mi = 0; mi < 2; mi++) {
                    mma_f16(O[mi][2*p],   pa[mi][kt], r);
                    mma_f16(O[mi][2*p+1], pa[mi][kt], r + 2);
                }
            }
        }
    }

    const int r = lane >> 2, q = lane & 3;
#pragma unroll
    for (int mi = 0; mi < 2; mi++) {
        float inv0 = 1.0f / l[mi*2], inv1 = 1.0f / l[mi*2+1];
        int t0 = qt * 128 + wid * 32 + mi * 16 + r;
#pragma unroll
        for (int nt = 0; nt < 8; nt++) {
            int d = nt * 8 + 2 * q;
            size_t i0 = ((size_t)(t0 * 2 + b)) * EMBED + h * 64 + d;
            size_t i1 = ((size_t)((t0 + 8) * 2 + b)) * EMBED + h * 64 + d;
            *(__half2*)(oh + i0) = __floats2half2_rn(O[mi][nt][0] * inv0,
                                                     O[mi][nt][1] * inv0);
            *(__half2*)(oh + i1) = __floats2half2_rn(O[mi][nt][2] * inv1,
                                                     O[mi][nt][3] * inv1);
        }
    }
}

// ---------------------------------------------------------------------------
extern "C" void kernel_launch(void* const* d_in, const int* in_sizes, int n_in,
                              void* d_out, int out_size)
{
    const float* x     = (const float*)d_in[0];
    const float* w_in  = (const float*)d_in[1];
    const float* b_in  = (const float*)d_in[2];
    const float* w_out = (const float*)d_in[3];
    const float* b_out = (const float*)d_in[4];
    float* out = (float*)d_out;

    void *xh, *winh, *woh, *qkvh, *ah;
    cudaGetSymbolAddress(&xh, g_xh);
    cudaGetSymbolAddress(&winh, g_winh);
    cudaGetSymbolAddress(&woh, g_woh);
    cudaGetSymbolAddress(&qkvh, g_qkvh);
    cudaGetSymbolAddress(&ah, g_ah);

    const int gemm_smem = 2 * GSTG;                   // 73728
    const int attn_smem = QSTG + 4 * ATBF;            // 55296
    cudaFuncSetAttribute(gemm_f16<0>,
        cudaFuncAttributeMaxDynamicSharedMemorySize, gemm_smem);
    cudaFuncSetAttribute(gemm_f16<2>,
        cudaFuncAttributeMaxDynamicSharedMemorySize, gemm_smem);
    cudaFuncSetAttribute(attn_f16,
        cudaFuncAttributeMaxDynamicSharedMemorySize, attn_smem);

    int n8 = MROWS * EMBED / 8;
    conv_f16<<<(n8 + 255) / 256, 256>>>(x, (__half*)xh, n8);
    n8 = QKV_N * EMBED / 8;
    conv_f16<<<(n8 + 255) / 256, 256>>>(w_in, (__half*)winh, n8);
    n8 = EMBED * EMBED / 8;
    conv_f16<<<(n8 + 255) / 256, 256>>>(w_out, (__half*)woh, n8);

    // 1) QKV projection -> fp16 qkv
    gemm_f16<2><<<dim3(QKV_N / 128, MROWS / 128), 256, gemm_smem>>>(
        (const __half*)xh, (const __half*)winh, b_in,
        nullptr, (__half*)qkvh, QKV_N, EMBED);

    // 2) attention -> fp16
    attn_f16<<<dim3(TLEN / 128, BSZ * NHEAD), 128, attn_smem>>>(
        (const __half*)qkvh, (__half*)ah);

    // 3) output projection -> fp32 out
    gemm_f16<0><<<dim3(EMBED / 128, MROWS / 128), 256, gemm_smem>>>(
        (const __half*)ah, (const __half*)woh, b_out,
        out, nullptr, EMBED, EMBED);
}

// round 15
// speedup vs baseline: 1.2140x; 1.0632x over previous
#include <cuda_runtime.h>
#include <cuda_fp16.h>
#include <math_constants.h>
#include <cstdint>

// ---------------------------------------------------------------------------
// MultiheadAttention (T=2048, B=2, E=1024, H=16, D=64) fp32, all-fp16 HMMA.
// R15: attention q-tile 64 / 4 warps (3 CTAs/SM, less wave-tail waste);
// single merged conversion kernel; GEMMs = R14 (BK=64, 8 warps, 2 CTAs/SM).
// ---------------------------------------------------------------------------

#define EMBED   1024
#define NHEAD   16
#define HDIM    64
#define TLEN    2048
#define BSZ     2
#define MROWS   4096
#define QKV_N   3072

// ------------------------------- scratch -----------------------------------
__device__ __half g_xh  [(size_t)MROWS * EMBED];
__device__ __half g_winh[(size_t)QKV_N * EMBED];
__device__ __half g_woh [(size_t)EMBED * EMBED];
__device__ __half g_qkvh[(size_t)MROWS * QKV_N];
__device__ __half g_ah  [(size_t)MROWS * EMBED];

#define XN8   (MROWS * EMBED / 8)        // 524288
#define WIN8  (QKV_N * EMBED / 8)        // 393216
#define WO8   (EMBED * EMBED / 8)        // 131072

// --------------------------- asm helpers -----------------------------------
__device__ __forceinline__ uint32_t smem_u32(const void* p) {
    uint32_t a;
    asm("{ .reg .u64 t; cvta.to.shared.u64 t, %1; cvt.u32.u64 %0, t; }"
        : "=r"(a) : "l"(p));
    return a;
}
__device__ __forceinline__ void ldsm4(uint32_t* r, uint32_t a) {
    asm volatile("ldmatrix.sync.aligned.m8n8.x4.shared.b16 {%0,%1,%2,%3}, [%4];"
        : "=r"(r[0]), "=r"(r[1]), "=r"(r[2]), "=r"(r[3]) : "r"(a));
}
__device__ __forceinline__ void ldsm4t(uint32_t* r, uint32_t a) {
    asm volatile("ldmatrix.sync.aligned.m8n8.x4.trans.shared.b16 {%0,%1,%2,%3}, [%4];"
        : "=r"(r[0]), "=r"(r[1]), "=r"(r[2]), "=r"(r[3]) : "r"(a));
}
__device__ __forceinline__ void mma_f16(float* c, const uint32_t* a, const uint32_t* b) {
    asm volatile(
        "mma.sync.aligned.m16n8k16.row.col.f32.f16.f16.f32 "
        "{%0,%1,%2,%3}, {%4,%5,%6,%7}, {%8,%9}, {%0,%1,%2,%3};"
        : "+f"(c[0]), "+f"(c[1]), "+f"(c[2]), "+f"(c[3])
        : "r"(a[0]), "r"(a[1]), "r"(a[2]), "r"(a[3]), "r"(b[0]), "r"(b[1]));
}
__device__ __forceinline__ void cpa16(uint32_t dst, const void* src) {
    asm volatile("cp.async.cg.shared.global [%0], [%1], 16;" :: "r"(dst), "l"(src));
}
#define CP_COMMIT() asm volatile("cp.async.commit_group;")
#define CP_WAIT0()  asm volatile("cp.async.wait_group 0;")

__device__ __forceinline__ uint32_t packh(float x, float y) {
    __half2 t = __floats2half2_rn(x, y);
    return *(uint32_t*)&t;
}
__device__ __forceinline__ uint32_t h2ex2(uint32_t x) {
    uint32_t y;
    asm("ex2.approx.f16x2 %0, %1;" : "=r"(y) : "r"(x));
    return y;
}

// ---------------------------------------------------------------------------
// One merged fp32->fp16 conversion over x, w_in, w_out (single launch).
// ---------------------------------------------------------------------------
__global__ void __launch_bounds__(256) conv_all(
    const float* __restrict__ x, const float* __restrict__ w_in,
    const float* __restrict__ w_out,
    __half* __restrict__ xh, __half* __restrict__ winh,
    __half* __restrict__ woh)
{
    int i = blockIdx.x * 256 + threadIdx.x;
    const float* src;
    __half* dst;
    int off;
    if (i < XN8)                 { src = x;     dst = xh;   off = i; }
    else if (i < XN8 + WIN8)     { src = w_in;  dst = winh; off = i - XN8; }
    else if (i < XN8 + WIN8 + WO8){ src = w_out; dst = woh;  off = i - XN8 - WIN8; }
    else return;
    float4 a = *(const float4*)(src + (size_t)off * 8);
    float4 b = *(const float4*)(src + (size_t)off * 8 + 4);
    __half2 h[4];
    h[0] = __floats2half2_rn(a.x, a.y); h[1] = __floats2half2_rn(a.z, a.w);
    h[2] = __floats2half2_rn(b.x, b.y); h[3] = __floats2half2_rn(b.z, b.w);
    *(uint4*)(dst + (size_t)off * 8) = *(uint4*)h;
}

// ---------------------------------------------------------------------------
// fp16 GEMM-NT + bias (R14 config): 128x128 CTA tile, BK=64, 8 warps (2x4),
// warp tile 64x32, cp.async 2-stage. MODE 0: fp32 out.  MODE 2: fp16 out.
// ---------------------------------------------------------------------------
#define GST    72
#define GTILE  (128 * GST * 2)       // 18432 B
#define GSTG   (2 * GTILE)           // 36864 B per stage

template<int MODE>
__global__ void __launch_bounds__(256) gemm_f16(
    const __half* __restrict__ A, const __half* __restrict__ B,
    const float* __restrict__ bias, float* __restrict__ Cf,
    __half* __restrict__ Ch, int N, int K)
{
    extern __shared__ char smem[];
    const uint32_t sbase = smem_u32(smem);
    const int tid = threadIdx.x, wid = tid >> 5, lane = tid & 31;
    const int bm = blockIdx.y, bn = blockIdx.x;
    const int wm = wid >> 2, wn = wid & 3;

    float acc[4][4][4];
#pragma unroll
    for (int a = 0; a < 4; a++)
#pragma unroll
        for (int b = 0; b < 4; b++)
#pragma unroll
            for (int c = 0; c < 4; c++) acc[a][b][c] = 0.0f;

    auto prefetch = [&](int it) {
        const int k0 = it << 6;
        const int buf = it & 1;
#pragma unroll
        for (int i = 0; i < 8; i++) {
            int g = tid + i * 256;
            int t = g >> 10;
            int c = g & 1023;
            int row = c >> 3, ch = c & 7;
            const __half* P = t ? B : A;
            int rb = t ? bn * 128 : bm * 128;
            const void* src = P + (size_t)(rb + row) * K + k0 + ch * 8;
            uint32_t dst = sbase + buf * GSTG + t * GTILE
                         + (row * GST + ch * 8) * 2;
            cpa16(dst, src);
        }
        CP_COMMIT();
    };

    const int niter = K >> 6;
    prefetch(0);
    for (int it = 0; it < niter; it++) {
        CP_WAIT0();
        __syncthreads();
        if (it + 1 < niter) prefetch(it + 1);

        const uint32_t tA = sbase + (it & 1) * GSTG;
        const uint32_t tB = tA + GTILE;

        const int ar = lane & 15, ac = (lane >> 4) * 8;
        const int br = (lane & 7) + ((lane & 16) ? 8 : 0);
        const int bc = (lane & 8) ? 8 : 0;

#pragma unroll
        for (int ks = 0; ks < 4; ks++) {
            const int k0 = ks * 16;
            uint32_t ah[4][4], bh[4][2];
#pragma unroll
            for (int mi = 0; mi < 4; mi++)
                ldsm4(ah[mi], tA + ((wm * 64 + mi * 16 + ar) * GST + k0 + ac) * 2);
#pragma unroll
            for (int p = 0; p < 2; p++) {
                uint32_t r[4];
                ldsm4(r, tB + ((wn * 32 + p * 16 + br) * GST + k0 + bc) * 2);
                bh[2*p][0] = r[0]; bh[2*p][1] = r[1];
                bh[2*p+1][0] = r[2]; bh[2*p+1][1] = r[3];
            }
#pragma unroll
            for (int mi = 0; mi < 4; mi++)
#pragma unroll
                for (int ni = 0; ni < 4; ni++)
                    mma_f16(acc[mi][ni], ah[mi], bh[ni]);
        }
    }

    const int r = lane >> 2, q = lane & 3;
#pragma unroll
    for (int mi = 0; mi < 4; mi++) {
#pragma unroll
        for (int ni = 0; ni < 4; ni++) {
            int row = bm * 128 + wm * 64 + mi * 16 + r;
            int col = bn * 128 + wn * 32 + ni * 8 + 2 * q;
            float b0 = bias[col], b1 = bias[col + 1];
            float v0 = acc[mi][ni][0] + b0, v1 = acc[mi][ni][1] + b1;
            float v2 = acc[mi][ni][2] + b0, v3 = acc[mi][ni][3] + b1;
            if (MODE == 0) {
                *(float2*)(Cf + (size_t)row * N + col)       = make_float2(v0, v1);
                *(float2*)(Cf + (size_t)(row + 8) * N + col) = make_float2(v2, v3);
            } else {
                *(__half2*)(Ch + (size_t)row * N + col)       = __floats2half2_rn(v0, v1);
                *(__half2*)(Ch + (size_t)(row + 8) * N + col) = __floats2half2_rn(v2, v3);
            }
        }
    }
}

// ---------------------------------------------------------------------------
// Flash attention: q-tile 64, 4 warps (128 threads), warp w owns q rows
// 16w..16w+15. fp16 HMMA, log2-domain softmax. 1024 CTAs -> ~3 CTAs/SM.
// smem: Q 64x72 (9216) + 2x(K,V) 64x72 (4x9216) = 46080 B.
// ---------------------------------------------------------------------------
#define AST  72
#define ATBF (64 * AST * 2)     // 9216 B per tile
#define QSTG (64 * AST * 2)     // 9216 B

__global__ void __launch_bounds__(128) attn_f16(
    const __half* __restrict__ qkv, __half* __restrict__ oh)
{
    extern __shared__ char smem[];
    const uint32_t sb  = smem_u32(smem);
    const uint32_t sQ  = sb;
    const uint32_t sKV = sb + QSTG;

    const int tid = threadIdx.x, wid = tid >> 5, lane = tid & 31;
    const int qt = blockIdx.x, bh = blockIdx.y, b = bh >> 4, h = bh & 15;

    // K tile + V tile per stage = 1024 x 16B transfers, 8/thread.
    auto pf = [&](int st) {
        const int buf = st & 1;
#pragma unroll
        for (int i = 0; i < 8; i++) {
            int c  = tid + i * 128;        // 0..1023
            int kv = c >> 9;               // 0=K, 1=V
            int e  = c & 511;
            int row = e >> 3, ch = e & 7;
            const void* src = qkv + ((size_t)((st * 64 + row) * 2 + b)) * QKV_N
                            + (kv ? 2 * EMBED : EMBED) + h * 64 + ch * 8;
            uint32_t dst = sKV + (buf * 2 + kv) * ATBF + (row * AST + ch * 8) * 2;
            cpa16(dst, src);
        }
        CP_COMMIT();
    };

    pf(0);

    // Q tile: 64 rows, 512 x 16B transfers, 4/thread. Scale 0.125*log2(e).
    const __half2 s2 = __floats2half2_rn(0.1803368801f, 0.1803368801f);
#pragma unroll
    for (int i = 0; i < 4; i++) {
        int c = tid + i * 128;             // 0..511
        int row = c >> 3, ch = c & 7;
        int t = qt * 64 + row;
        uint4 v = *(const uint4*)(qkv + ((size_t)(t * 2 + b)) * QKV_N + h * 64 + ch * 8);
        __half2* p = (__half2*)&v;
#pragma unroll
        for (int j = 0; j < 4; j++) p[j] = __hmul2(p[j], s2);
        *(uint4*)(smem + (row * AST + ch * 8) * 2) = v;
    }
    __syncthreads();

    uint32_t qf[4][4];
    {
        const int ar = lane & 15, ac = (lane >> 4) * 8;
#pragma unroll
        for (int kt = 0; kt < 4; kt++)
            ldsm4(qf[kt], sQ + ((wid * 16 + ar) * AST + kt * 16 + ac) * 2);
    }

    float O[8][4];
#pragma unroll
    for (int i = 0; i < 8; i++)
#pragma unroll
        for (int j = 0; j < 4; j++) O[i][j] = 0.0f;
    float m0 = -CUDART_INF_F, m1 = -CUDART_INF_F, l0 = 0.0f, l1 = 0.0f;

    const int br = (lane & 7) + ((lane & 16) ? 8 : 0);
    const int bc = (lane & 8) ? 8 : 0;
    const int vr = lane & 15, vc = (lane >> 4) * 8;

    for (int st = 0; st < TLEN / 64; st++) {
        CP_WAIT0();
        __syncthreads();
        if (st + 1 < TLEN / 64) pf(st + 1);

        const uint32_t sK = sKV + ((st & 1) * 2) * ATBF;
        const uint32_t sV = sK + ATBF;

        float s4[8][4];
#pragma unroll
        for (int i = 0; i < 8; i++)
#pragma unroll
            for (int j = 0; j < 4; j++) s4[i][j] = 0.0f;

#pragma unroll
        for (int kt = 0; kt < 4; kt++) {
            uint32_t kh[8][2];
#pragma unroll
            for (int p = 0; p < 4; p++) {
                uint32_t r[4];
                ldsm4(r, sK + ((p * 16 + br) * AST + kt * 16 + bc) * 2);
                kh[2*p][0] = r[0]; kh[2*p][1] = r[1];
                kh[2*p+1][0] = r[2]; kh[2*p+1][1] = r[3];
            }
#pragma unroll
            for (int nt = 0; nt < 8; nt++)
                mma_f16(s4[nt], qf[kt], kh[nt]);
        }

        float mx0 = -CUDART_INF_F, mx1 = -CUDART_INF_F;
#pragma unroll
        for (int nt = 0; nt < 8; nt++) {
            mx0 = fmaxf(mx0, fmaxf(s4[nt][0], s4[nt][1]));
            mx1 = fmaxf(mx1, fmaxf(s4[nt][2], s4[nt][3]));
        }
        mx0 = fmaxf(mx0, __shfl_xor_sync(0xffffffffu, mx0, 1));
        mx0 = fmaxf(mx0, __shfl_xor_sync(0xffffffffu, mx0, 2));
        mx1 = fmaxf(mx1, __shfl_xor_sync(0xffffffffu, mx1, 1));
        mx1 = fmaxf(mx1, __shfl_xor_sync(0xffffffffu, mx1, 2));

        float mn0 = fmaxf(m0, mx0), mn1 = fmaxf(m1, mx1);
        float a0 = exp2f(m0 - mn0), a1 = exp2f(m1 - mn1);
        m0 = mn0; m1 = mn1;

        uint32_t pa[4][4];
        float sum0 = 0.0f, sum1 = 0.0f;
#pragma unroll
        for (int jj = 0; jj < 4; jj++) {
            pa[jj][0] = h2ex2(packh(s4[2*jj][0]   - mn0, s4[2*jj][1]   - mn0));
            pa[jj][1] = h2ex2(packh(s4[2*jj][2]   - mn1, s4[2*jj][3]   - mn1));
            pa[jj][2] = h2ex2(packh(s4[2*jj+1][0] - mn0, s4[2*jj+1][1] - mn0));
            pa[jj][3] = h2ex2(packh(s4[2*jj+1][2] - mn1, s4[2*jj+1][3] - mn1));
            float2 f;
            f = __half22float2(*(__half2*)&pa[jj][0]); sum0 += f.x + f.y;
            f = __half22float2(*(__half2*)&pa[jj][2]); sum0 += f.x + f.y;
            f = __half22float2(*(__half2*)&pa[jj][1]); sum1 += f.x + f.y;
            f = __half22float2(*(__half2*)&pa[jj][3]); sum1 += f.x + f.y;
        }
        sum0 += __shfl_xor_sync(0xffffffffu, sum0, 1);
        sum0 += __shfl_xor_sync(0xffffffffu, sum0, 2);
        sum1 += __shfl_xor_sync(0xffffffffu, sum1, 1);
        sum1 += __shfl_xor_sync(0xffffffffu, sum1, 2);
        l0 = l0 * a0 + sum0;
        l1 = l1 * a1 + sum1;
#pragma unroll
        for (int nt = 0; nt < 8; nt++) {
            O[nt][0] *= a0; O[nt][1] *= a0; O[nt][2] *= a1; O[nt][3] *= a1;
        }

#pragma unroll
        for (int kt = 0; kt < 4; kt++) {
#pragma unroll
            for (int p = 0; p < 4; p++) {
                uint32_t r[4];
                ldsm4t(r, sV + ((kt * 16 + vr) * AST + p * 16 + vc) * 2);
                mma_f16(O[2*p],   pa[kt], r);
                mma_f16(O[2*p+1], pa[kt], r + 2);
            }
        }
    }

    const float inv0 = 1.0f / l0, inv1 = 1.0f / l1;
    const int r = lane >> 2, q = lane & 3;
    const int t0 = qt * 64 + wid * 16 + r;
#pragma unroll
    for (int nt = 0; nt < 8; nt++) {
        int d = nt * 8 + 2 * q;
        size_t i0 = ((size_t)(t0 * 2 + b)) * EMBED + h * 64 + d;
        size_t i1 = ((size_t)((t0 + 8) * 2 + b)) * EMBED + h * 64 + d;
        *(__half2*)(oh + i0) = __floats2half2_rn(O[nt][0] * inv0, O[nt][1] * inv0);
        *(__half2*)(oh + i1) = __floats2half2_rn(O[nt][2] * inv1, O[nt][3] * inv1);
    }
}

// ---------------------------------------------------------------------------
extern "C" void kernel_launch(void* const* d_in, const int* in_sizes, int n_in,
                              void* d_out, int out_size)
{
    const float* x     = (const float*)d_in[0];
    const float* w_in  = (const float*)d_in[1];
    const float* b_in  = (const float*)d_in[2];
    const float* w_out = (const float*)d_in[3];
    const float* b_out = (const float*)d_in[4];
    float* out = (float*)d_out;

    void *xh, *winh, *woh, *qkvh, *ah;
    cudaGetSymbolAddress(&xh, g_xh);
    cudaGetSymbolAddress(&winh, g_winh);
    cudaGetSymbolAddress(&woh, g_woh);
    cudaGetSymbolAddress(&qkvh, g_qkvh);
    cudaGetSymbolAddress(&ah, g_ah);

    const int gemm_smem = 2 * GSTG;                   // 73728
    const int attn_smem = QSTG + 4 * ATBF;            // 46080
    cudaFuncSetAttribute(gemm_f16<0>,
        cudaFuncAttributeMaxDynamicSharedMemorySize, gemm_smem);
    cudaFuncSetAttribute(gemm_f16<2>,
        cudaFuncAttributeMaxDynamicSharedMemorySize, gemm_smem);
    cudaFuncSetAttribute(attn_f16,
        cudaFuncAttributeMaxDynamicSharedMemorySize, attn_smem);

    // merged conversions (one launch)
    {
        int total = XN8 + WIN8 + WO8;
        conv_all<<<(total + 255) / 256, 256>>>(
            x, w_in, w_out, (__half*)xh, (__half*)winh, (__half*)woh);
    }

    // 1) QKV projection -> fp16 qkv
    gemm_f16<2><<<dim3(QKV_N / 128, MROWS / 128), 256, gemm_smem>>>(
        (const __half*)xh, (const __half*)winh, b_in,
        nullptr, (__half*)qkvh, QKV_N, EMBED);

    // 2) attention -> fp16 (q-tile 64, 1024 CTAs)
    attn_f16<<<dim3(TLEN / 64, BSZ * NHEAD), 128, attn_smem>>>(
        (const __half*)qkvh, (__half*)ah);

    // 3) output projection -> fp32 out
    gemm_f16<0><<<dim3(EMBED / 128, MROWS / 128), 256, gemm_smem>>>(
        (const __half*)ah, (const __half*)woh, b_out,
        out, nullptr, EMBED, EMBED);
}

// round 16
// speedup vs baseline: 1.2254x; 1.0094x over previous
#include <cuda_runtime.h>
#include <cuda_fp16.h>
#include <math_constants.h>
#include <cstdint>

// ---------------------------------------------------------------------------
// MultiheadAttention (T=2048, B=2, E=1024, H=16, D=64) fp32, all-fp16 HMMA.
// R16: attention forced to 4 CTAs/SM (__launch_bounds__(128,4)) to cut
// wave-tail waste 77%->86%. GEMMs/conv unchanged from R15.
// ---------------------------------------------------------------------------

#define EMBED   1024
#define NHEAD   16
#define HDIM    64
#define TLEN    2048
#define BSZ     2
#define MROWS   4096
#define QKV_N   3072

// ------------------------------- scratch -----------------------------------
__device__ __half g_xh  [(size_t)MROWS * EMBED];
__device__ __half g_winh[(size_t)QKV_N * EMBED];
__device__ __half g_woh [(size_t)EMBED * EMBED];
__device__ __half g_qkvh[(size_t)MROWS * QKV_N];
__device__ __half g_ah  [(size_t)MROWS * EMBED];

#define XN8   (MROWS * EMBED / 8)        // 524288
#define WIN8  (QKV_N * EMBED / 8)        // 393216
#define WO8   (EMBED * EMBED / 8)        // 131072

// --------------------------- asm helpers -----------------------------------
__device__ __forceinline__ uint32_t smem_u32(const void* p) {
    uint32_t a;
    asm("{ .reg .u64 t; cvta.to.shared.u64 t, %1; cvt.u32.u64 %0, t; }"
        : "=r"(a) : "l"(p));
    return a;
}
__device__ __forceinline__ void ldsm4(uint32_t* r, uint32_t a) {
    asm volatile("ldmatrix.sync.aligned.m8n8.x4.shared.b16 {%0,%1,%2,%3}, [%4];"
        : "=r"(r[0]), "=r"(r[1]), "=r"(r[2]), "=r"(r[3]) : "r"(a));
}
__device__ __forceinline__ void ldsm4t(uint32_t* r, uint32_t a) {
    asm volatile("ldmatrix.sync.aligned.m8n8.x4.trans.shared.b16 {%0,%1,%2,%3}, [%4];"
        : "=r"(r[0]), "=r"(r[1]), "=r"(r[2]), "=r"(r[3]) : "r"(a));
}
__device__ __forceinline__ void mma_f16(float* c, const uint32_t* a, const uint32_t* b) {
    asm volatile(
        "mma.sync.aligned.m16n8k16.row.col.f32.f16.f16.f32 "
        "{%0,%1,%2,%3}, {%4,%5,%6,%7}, {%8,%9}, {%0,%1,%2,%3};"
        : "+f"(c[0]), "+f"(c[1]), "+f"(c[2]), "+f"(c[3])
        : "r"(a[0]), "r"(a[1]), "r"(a[2]), "r"(a[3]), "r"(b[0]), "r"(b[1]));
}
__device__ __forceinline__ void cpa16(uint32_t dst, const void* src) {
    asm volatile("cp.async.cg.shared.global [%0], [%1], 16;" :: "r"(dst), "l"(src));
}
#define CP_COMMIT() asm volatile("cp.async.commit_group;")
#define CP_WAIT0()  asm volatile("cp.async.wait_group 0;")

__device__ __forceinline__ uint32_t packh(float x, float y) {
    __half2 t = __floats2half2_rn(x, y);
    return *(uint32_t*)&t;
}
__device__ __forceinline__ uint32_t h2ex2(uint32_t x) {
    uint32_t y;
    asm("ex2.approx.f16x2 %0, %1;" : "=r"(y) : "r"(x));
    return y;
}

// ---------------------------------------------------------------------------
// One merged fp32->fp16 conversion over x, w_in, w_out (single launch).
// ---------------------------------------------------------------------------
__global__ void __launch_bounds__(256) conv_all(
    const float* __restrict__ x, const float* __restrict__ w_in,
    const float* __restrict__ w_out,
    __half* __restrict__ xh, __half* __restrict__ winh,
    __half* __restrict__ woh)
{
    int i = blockIdx.x * 256 + threadIdx.x;
    const float* src;
    __half* dst;
    int off;
    if (i < XN8)                 { src = x;     dst = xh;   off = i; }
    else if (i < XN8 + WIN8)     { src = w_in;  dst = winh; off = i - XN8; }
    else if (i < XN8 + WIN8 + WO8){ src = w_out; dst = woh;  off = i - XN8 - WIN8; }
    else return;
    float4 a = *(const float4*)(src + (size_t)off * 8);
    float4 b = *(const float4*)(src + (size_t)off * 8 + 4);
    __half2 h[4];
    h[0] = __floats2half2_rn(a.x, a.y); h[1] = __floats2half2_rn(a.z, a.w);
    h[2] = __floats2half2_rn(b.x, b.y); h[3] = __floats2half2_rn(b.z, b.w);
    *(uint4*)(dst + (size_t)off * 8) = *(uint4*)h;
}

// ---------------------------------------------------------------------------
// fp16 GEMM-NT + bias: 128x128 CTA tile, BK=64, 8 warps (2x4), warp tile
// 64x32, cp.async 2-stage. MODE 0: fp32 out.  MODE 2: fp16 out.
// ---------------------------------------------------------------------------
#define GST    72
#define GTILE  (128 * GST * 2)       // 18432 B
#define GSTG   (2 * GTILE)           // 36864 B per stage

template<int MODE>
__global__ void __launch_bounds__(256) gemm_f16(
    const __half* __restrict__ A, const __half* __restrict__ B,
    const float* __restrict__ bias, float* __restrict__ Cf,
    __half* __restrict__ Ch, int N, int K)
{
    extern __shared__ char smem[];
    const uint32_t sbase = smem_u32(smem);
    const int tid = threadIdx.x, wid = tid >> 5, lane = tid & 31;
    const int bm = blockIdx.y, bn = blockIdx.x;
    const int wm = wid >> 2, wn = wid & 3;

    float acc[4][4][4];
#pragma unroll
    for (int a = 0; a < 4; a++)
#pragma unroll
        for (int b = 0; b < 4; b++)
#pragma unroll
            for (int c = 0; c < 4; c++) acc[a][b][c] = 0.0f;

    auto prefetch = [&](int it) {
        const int k0 = it << 6;
        const int buf = it & 1;
#pragma unroll
        for (int i = 0; i < 8; i++) {
            int g = tid + i * 256;
            int t = g >> 10;
            int c = g & 1023;
            int row = c >> 3, ch = c & 7;
            const __half* P = t ? B : A;
            int rb = t ? bn * 128 : bm * 128;
            const void* src = P + (size_t)(rb + row) * K + k0 + ch * 8;
            uint32_t dst = sbase + buf * GSTG + t * GTILE
                         + (row * GST + ch * 8) * 2;
            cpa16(dst, src);
        }
        CP_COMMIT();
    };

    const int niter = K >> 6;
    prefetch(0);
    for (int it = 0; it < niter; it++) {
        CP_WAIT0();
        __syncthreads();
        if (it + 1 < niter) prefetch(it + 1);

        const uint32_t tA = sbase + (it & 1) * GSTG;
        const uint32_t tB = tA + GTILE;

        const int ar = lane & 15, ac = (lane >> 4) * 8;
        const int br = (lane & 7) + ((lane & 16) ? 8 : 0);
        const int bc = (lane & 8) ? 8 : 0;

#pragma unroll
        for (int ks = 0; ks < 4; ks++) {
            const int k0 = ks * 16;
            uint32_t ah[4][4], bh[4][2];
#pragma unroll
            for (int mi = 0; mi < 4; mi++)
                ldsm4(ah[mi], tA + ((wm * 64 + mi * 16 + ar) * GST + k0 + ac) * 2);
#pragma unroll
            for (int p = 0; p < 2; p++) {
                uint32_t r[4];
                ldsm4(r, tB + ((wn * 32 + p * 16 + br) * GST + k0 + bc) * 2);
                bh[2*p][0] = r[0]; bh[2*p][1] = r[1];
                bh[2*p+1][0] = r[2]; bh[2*p+1][1] = r[3];
            }
#pragma unroll
            for (int mi = 0; mi < 4; mi++)
#pragma unroll
                for (int ni = 0; ni < 4; ni++)
                    mma_f16(acc[mi][ni], ah[mi], bh[ni]);
        }
    }

    const int r = lane >> 2, q = lane & 3;
#pragma unroll
    for (int mi = 0; mi < 4; mi++) {
#pragma unroll
        for (int ni = 0; ni < 4; ni++) {
            int row = bm * 128 + wm * 64 + mi * 16 + r;
            int col = bn * 128 + wn * 32 + ni * 8 + 2 * q;
            float b0 = bias[col], b1 = bias[col + 1];
            float v0 = acc[mi][ni][0] + b0, v1 = acc[mi][ni][1] + b1;
            float v2 = acc[mi][ni][2] + b0, v3 = acc[mi][ni][3] + b1;
            if (MODE == 0) {
                *(float2*)(Cf + (size_t)row * N + col)       = make_float2(v0, v1);
                *(float2*)(Cf + (size_t)(row + 8) * N + col) = make_float2(v2, v3);
            } else {
                *(__half2*)(Ch + (size_t)row * N + col)       = __floats2half2_rn(v0, v1);
                *(__half2*)(Ch + (size_t)(row + 8) * N + col) = __floats2half2_rn(v2, v3);
            }
        }
    }
}

// ---------------------------------------------------------------------------
// Flash attention: q-tile 64, 4 warps (128 threads), 4 CTAs/SM target.
// fp16 HMMA, log2-domain softmax.
// smem: Q 64x72 (9216) + 2x(K,V) 64x72 (4x9216) = 46080 B.
// ---------------------------------------------------------------------------
#define AST  72
#define ATBF (64 * AST * 2)     // 9216 B per tile
#define QSTG (64 * AST * 2)     // 9216 B

__global__ void __launch_bounds__(128, 4) attn_f16(
    const __half* __restrict__ qkv, __half* __restrict__ oh)
{
    extern __shared__ char smem[];
    const uint32_t sb  = smem_u32(smem);
    const uint32_t sQ  = sb;
    const uint32_t sKV = sb + QSTG;

    const int tid = threadIdx.x, wid = tid >> 5, lane = tid & 31;
    const int qt = blockIdx.x, bh = blockIdx.y, b = bh >> 4, h = bh & 15;

    auto pf = [&](int st) {
        const int buf = st & 1;
#pragma unroll
        for (int i = 0; i < 8; i++) {
            int c  = tid + i * 128;        // 0..1023
            int kv = c >> 9;               // 0=K, 1=V
            int e  = c & 511;
            int row = e >> 3, ch = e & 7;
            const void* src = qkv + ((size_t)((st * 64 + row) * 2 + b)) * QKV_N
                            + (kv ? 2 * EMBED : EMBED) + h * 64 + ch * 8;
            uint32_t dst = sKV + (buf * 2 + kv) * ATBF + (row * AST + ch * 8) * 2;
            cpa16(dst, src);
        }
        CP_COMMIT();
    };

    pf(0);

    const __half2 s2 = __floats2half2_rn(0.1803368801f, 0.1803368801f);
#pragma unroll
    for (int i = 0; i < 4; i++) {
        int c = tid + i * 128;             // 0..511
        int row = c >> 3, ch = c & 7;
        int t = qt * 64 + row;
        uint4 v = *(const uint4*)(qkv + ((size_t)(t * 2 + b)) * QKV_N + h * 64 + ch * 8);
        __half2* p = (__half2*)&v;
#pragma unroll
        for (int j = 0; j < 4; j++) p[j] = __hmul2(p[j], s2);
        *(uint4*)(smem + (row * AST + ch * 8) * 2) = v;
    }
    __syncthreads();

    uint32_t qf[4][4];
    {
        const int ar = lane & 15, ac = (lane >> 4) * 8;
#pragma unroll
        for (int kt = 0; kt < 4; kt++)
            ldsm4(qf[kt], sQ + ((wid * 16 + ar) * AST + kt * 16 + ac) * 2);
    }

    float O[8][4];
#pragma unroll
    for (int i = 0; i < 8; i++)
#pragma unroll
        for (int j = 0; j < 4; j++) O[i][j] = 0.0f;
    float m0 = -CUDART_INF_F, m1 = -CUDART_INF_F, l0 = 0.0f, l1 = 0.0f;

    const int br = (lane & 7) + ((lane & 16) ? 8 : 0);
    const int bc = (lane & 8) ? 8 : 0;
    const int vr = lane & 15, vc = (lane >> 4) * 8;

    for (int st = 0; st < TLEN / 64; st++) {
        CP_WAIT0();
        __syncthreads();
        if (st + 1 < TLEN / 64) pf(st + 1);

        const uint32_t sK = sKV + ((st & 1) * 2) * ATBF;
        const uint32_t sV = sK + ATBF;

        float s4[8][4];
#pragma unroll
        for (int i = 0; i < 8; i++)
#pragma unroll
            for (int j = 0; j < 4; j++) s4[i][j] = 0.0f;

#pragma unroll
        for (int kt = 0; kt < 4; kt++) {
            uint32_t kh[8][2];
#pragma unroll
            for (int p = 0; p < 4; p++) {
                uint32_t r[4];
                ldsm4(r, sK + ((p * 16 + br) * AST + kt * 16 + bc) * 2);
                kh[2*p][0] = r[0]; kh[2*p][1] = r[1];
                kh[2*p+1][0] = r[2]; kh[2*p+1][1] = r[3];
            }
#pragma unroll
            for (int nt = 0; nt < 8; nt++)
                mma_f16(s4[nt], qf[kt], kh[nt]);
        }

        float mx0 = -CUDART_INF_F, mx1 = -CUDART_INF_F;
#pragma unroll
        for (int nt = 0; nt < 8; nt++) {
            mx0 = fmaxf(mx0, fmaxf(s4[nt][0], s4[nt][1]));
            mx1 = fmaxf(mx1, fmaxf(s4[nt][2], s4[nt][3]));
        }
        mx0 = fmaxf(mx0, __shfl_xor_sync(0xffffffffu, mx0, 1));
        mx0 = fmaxf(mx0, __shfl_xor_sync(0xffffffffu, mx0, 2));
        mx1 = fmaxf(mx1, __shfl_xor_sync(0xffffffffu, mx1, 1));
        mx1 = fmaxf(mx1, __shfl_xor_sync(0xffffffffu, mx1, 2));

        float mn0 = fmaxf(m0, mx0), mn1 = fmaxf(m1, mx1);
        float a0 = exp2f(m0 - mn0), a1 = exp2f(m1 - mn1);
        m0 = mn0; m1 = mn1;

        uint32_t pa[4][4];
        float sum0 = 0.0f, sum1 = 0.0f;
#pragma unroll
        for (int jj = 0; jj < 4; jj++) {
            pa[jj][0] = h2ex2(packh(s4[2*jj][0]   - mn0, s4[2*jj][1]   - mn0));
            pa[jj][1] = h2ex2(packh(s4[2*jj][2]   - mn1, s4[2*jj][3]   - mn1));
            pa[jj][2] = h2ex2(packh(s4[2*jj+1][0] - mn0, s4[2*jj+1][1] - mn0));
            pa[jj][3] = h2ex2(packh(s4[2*jj+1][2] - mn1, s4[2*jj+1][3] - mn1));
            float2 f;
            f = __half22float2(*(__half2*)&pa[jj][0]); sum0 += f.x + f.y;
            f = __half22float2(*(__half2*)&pa[jj][2]); sum0 += f.x + f.y;
            f = __half22float2(*(__half2*)&pa[jj][1]); sum1 += f.x + f.y;
            f = __half22float2(*(__half2*)&pa[jj][3]); sum1 += f.x + f.y;
        }
        sum0 += __shfl_xor_sync(0xffffffffu, sum0, 1);
        sum0 += __shfl_xor_sync(0xffffffffu, sum0, 2);
        sum1 += __shfl_xor_sync(0xffffffffu, sum1, 1);
        sum1 += __shfl_xor_sync(0xffffffffu, sum1, 2);
        l0 = l0 * a0 + sum0;
        l1 = l1 * a1 + sum1;
#pragma unroll
        for (int nt = 0; nt < 8; nt++) {
            O[nt][0] *= a0; O[nt][1] *= a0; O[nt][2] *= a1; O[nt][3] *= a1;
        }

#pragma unroll
        for (int kt = 0; kt < 4; kt++) {
#pragma unroll
            for (int p = 0; p < 4; p++) {
                uint32_t r[4];
                ldsm4t(r, sV + ((kt * 16 + vr) * AST + p * 16 + vc) * 2);
                mma_f16(O[2*p],   pa[kt], r);
                mma_f16(O[2*p+1], pa[kt], r + 2);
            }
        }
    }

    const float inv0 = 1.0f / l0, inv1 = 1.0f / l1;
    const int r = lane >> 2, q = lane & 3;
    const int t0 = qt * 64 + wid * 16 + r;
#pragma unroll
    for (int nt = 0; nt < 8; nt++) {
        int d = nt * 8 + 2 * q;
        size_t i0 = ((size_t)(t0 * 2 + b)) * EMBED + h * 64 + d;
        size_t i1 = ((size_t)((t0 + 8) * 2 + b)) * EMBED + h * 64 + d;
        *(__half2*)(oh + i0) = __floats2half2_rn(O[nt][0] * inv0, O[nt][1] * inv0);
        *(__half2*)(oh + i1) = __floats2half2_rn(O[nt][2] * inv1, O[nt][3] * inv1);
    }
}

// ---------------------------------------------------------------------------
extern "C" void kernel_launch(void* const* d_in, const int* in_sizes, int n_in,
                              void* d_out, int out_size)
{
    const float* x     = (const float*)d_in[0];
    const float* w_in  = (const float*)d_in[1];
    const float* b_in  = (const float*)d_in[2];
    const float* w_out = (const float*)d_in[3];
    const float* b_out = (const float*)d_in[4];
    float* out = (float*)d_out;

    void *xh, *winh, *woh, *qkvh, *ah;
    cudaGetSymbolAddress(&xh, g_xh);
    cudaGetSymbolAddress(&winh, g_winh);
    cudaGetSymbolAddress(&woh, g_woh);
    cudaGetSymbolAddress(&qkvh, g_qkvh);
    cudaGetSymbolAddress(&ah, g_ah);

    const int gemm_smem = 2 * GSTG;                   // 73728
    const int attn_smem = QSTG + 4 * ATBF;            // 46080
    cudaFuncSetAttribute(gemm_f16<0>,
        cudaFuncAttributeMaxDynamicSharedMemorySize, gemm_smem);
    cudaFuncSetAttribute(gemm_f16<2>,
        cudaFuncAttributeMaxDynamicSharedMemorySize, gemm_smem);
    cudaFuncSetAttribute(attn_f16,
        cudaFuncAttributeMaxDynamicSharedMemorySize, attn_smem);

    {
        int total = XN8 + WIN8 + WO8;
        conv_all<<<(total + 255) / 256, 256>>>(
            x, w_in, w_out, (__half*)xh, (__half*)winh, (__half*)woh);
    }

    // 1) QKV projection -> fp16 qkv
    gemm_f16<2><<<dim3(QKV_N / 128, MROWS / 128), 256, gemm_smem>>>(
        (const __half*)xh, (const __half*)winh, b_in,
        nullptr, (__half*)qkvh, QKV_N, EMBED);

    // 2) attention -> fp16 (q-tile 64, 1024 CTAs)
    attn_f16<<<dim3(TLEN / 64, BSZ * NHEAD), 128, attn_smem>>>(
        (const __half*)qkvh, (__half*)ah);

    // 3) output projection -> fp32 out
    gemm_f16<0><<<dim3(EMBED / 128, MROWS / 128), 256, gemm_smem>>>(
        (const __half*)ah, (const __half*)woh, b_out,
        out, nullptr, EMBED, EMBED);
}